// round 2
// baseline (speedup 1.0000x reference)
#include <cuda_runtime.h>
#include <math.h>

#define BB 20
#define LL 20
#define VV 100000

// per-batch loss scratch (device global — no allocation allowed)
__device__ float g_loss[BB];

// One block per batch: gather P[b,:,:] (400 scattered loads) into smem,
// then warp 0 runs the anti-diagonal wavefront DP.
__global__ void calcs_batch_kernel(const float* __restrict__ topic_prob,
                                   const int* __restrict__ hard_label) {
    __shared__ int   s_lab[LL];
    __shared__ float sP[LL * LL];

    const int b = blockIdx.x;
    const int t = threadIdx.x;

    if (t < LL) s_lab[t] = hard_label[b * LL + t];
    __syncthreads();

    if (t < LL * LL) {
        int j = t / LL;
        int k = t - j * LL;
        int idx = s_lab[k];
        idx = min(max(idx, 0), VV - 1);              // jnp.clip
        sP[t] = topic_prob[(size_t)b * LL * VV + (size_t)j * VV + (size_t)idx];
    }
    __syncthreads();

    // Warp 0: wavefront DP. Lane k owns dp column k+1.
    // Cell (j+1, k+1) is computed at step tst = j + k:
    //   up   = dp[j  ][k+1] = my value from step tst-1          (v1)
    //   left = dp[j+1][k  ] = lane k-1 value from step tst-1    (shfl_up v1)
    //   diag = dp[j  ][k  ] = lane k-1 value from step tst-2    (shfl_up v2)
    if (t < 32) {
        const int k = t;
        unsigned mbits = __ballot_sync(0xFFFFFFFFu, (k < LL) && (s_lab[k & (LL-1)] >= 0));
        // (k & (LL-1)) only to keep lanes 20..31 in-bounds; their predicate is false anyway
        mbits &= (1u << LL) - 1u;
        const int len = __popc(mbits);

        float v1 = 0.0f, v2 = 0.0f;   // my last / second-to-last computed cell
        float final_v = 0.0f;

        #pragma unroll
        for (int step = 0; step < 2 * LL - 1; ++step) {
            float left = __shfl_up_sync(0xFFFFFFFFu, v1, 1);
            float diag = __shfl_up_sync(0xFFFFFFFFu, v2, 1);
            if (k == 0) { left = 0.0f; diag = 0.0f; }  // dp row/col 0 are zero
            const float up = v1;

            const int  j      = step - k;
            const bool active = (k < LL) && (j >= 0) && (j < LL);

            float newv1 = v1;
            if (active) {
                float p   = sP[j * LL + k];
                float val = p * (diag + 1.0f) + (1.0f - p) * fmaxf(left, up);
                unsigned ok = ((mbits >> j) & 1u) & ((mbits >> k) & 1u);
                val = ok ? val : 0.0f;
                newv1 = val;
                if ((j + 1 == len) && (k + 1 == len)) final_v = val;  // dp[len][len]
            }
            v2 = v1;
            v1 = newv1;
        }

        const int src = (len > 0) ? (len - 1) : 0;
        const float f = __shfl_sync(0xFFFFFFFFu, final_v, src);
        if (t == 0) {
            g_loss[b] = -logf(f / (float)len);
        }
    }
}

// Deterministic single-warp reduction over the 20 per-batch losses.
__global__ void calcs_reduce_kernel(float* __restrict__ out) {
    const int t = threadIdx.x;
    float v = (t < BB) ? g_loss[t] : 0.0f;
    #pragma unroll
    for (int off = 16; off > 0; off >>= 1)
        v += __shfl_down_sync(0xFFFFFFFFu, v, off);
    if (t == 0) out[0] = v / (float)BB;
}

extern "C" void kernel_launch(void* const* d_in, const int* in_sizes, int n_in,
                              void* d_out, int out_size) {
    const float* topic_prob = (const float*)d_in[0];
    const int*   hard_label = (const int*)d_in[1];
    float*       out        = (float*)d_out;

    calcs_batch_kernel<<<BB, 512>>>(topic_prob, hard_label);
    calcs_reduce_kernel<<<1, 32>>>(out);
}